// round 3
// baseline (speedup 1.0000x reference)
#include <cuda_runtime.h>
#include <math.h>

#define B 4
#define L 2048
#define D 2048
#define LC 128         // L-chunks for pass-1 partial reduction
#define LPC (L/LC)     // 16 rows per chunk
#define ICK 128        // col-term chunks
#define RPC (D/ICK)    // 16 rows per chunk
#define DT_STEP 0.01f
#define DEG 8

// ---- scratch (device globals, no allocation allowed) ----
__device__ float g_partial[B*LC*D];    // 4 MB  pass-1 partial sums [b][chunk][d]
__device__ float g_xmean[B*D];         // 32 KB
__device__ float g_t[B*D];             // 32 KB  t = H @ x_mean
__device__ float g_colpart[ICK*B*D];   // 4 MB  partial J_u^T t terms
__device__ float g_colsum[B*D];        // 32 KB
__device__ float g_delta[B*D];         // 32 KB  broadcast row update

// ============ Pass 1: partial column sums over L-chunks ============
__global__ void k_partial(const float* __restrict__ x) {
    int dt = blockIdx.x;            // d-tile: 0..1 (1024 d each)
    int lc = blockIdx.y;            // l-chunk: 0..LC-1
    int b  = blockIdx.z;
    int d  = dt*1024 + threadIdx.x*4;
    float4 acc = make_float4(0.f,0.f,0.f,0.f);
    size_t base = ((size_t)b*L + (size_t)lc*LPC)*D + d;
    const float4* xp = (const float4*)x;
    #pragma unroll
    for (int l = 0; l < LPC; ++l) {
        float4 v = xp[(base + (size_t)l*D) >> 2];
        acc.x += v.x; acc.y += v.y; acc.z += v.z; acc.w += v.w;
    }
    *(float4*)&g_partial[(size_t)(b*LC + lc)*D + d] = acc;
}

// ============ Finalize mean ============
__global__ void k_mean() {
    int idx = blockIdx.x*256 + threadIdx.x;   // 0..B*D-1
    int b = idx >> 11;
    int d = idx & (D-1);
    float s = 0.f;
    #pragma unroll 16
    for (int c = 0; c < LC; ++c)
        s += g_partial[(size_t)(b*LC + c)*D + d];
    g_xmean[idx] = s * (1.0f / (float)L);
}

// ============ GEMV 1: t[b,i] = sum_j h[i,j] * xmean[b,j] ============
// 2 rows/block, 4 warps per row (quarter-rows each) -> grid = D/2 = 1024 blocks
__global__ void __launch_bounds__(256) k_gemv1(const float* __restrict__ h) {
    __shared__ float s_part[8][4];
    int w = threadIdx.x >> 5, lane = threadIdx.x & 31;
    int row = blockIdx.x*2 + (w >> 2);
    int q   = w & 3;
    const float4* hp = (const float4*)(h + (size_t)row*D);
    const float4* m0 = (const float4*)(g_xmean + 0*D);
    const float4* m1 = (const float4*)(g_xmean + 1*D);
    const float4* m2 = (const float4*)(g_xmean + 2*D);
    const float4* m3 = (const float4*)(g_xmean + 3*D);
    float a0=0.f, a1=0.f, a2=0.f, a3=0.f;
    #pragma unroll
    for (int i = 0; i < 4; ++i) {
        int j4 = q*128 + i*32 + lane;
        float4 hv = hp[j4];
        float4 v0 = m0[j4], v1 = m1[j4], v2 = m2[j4], v3 = m3[j4];
        a0 += hv.x*v0.x + hv.y*v0.y + hv.z*v0.z + hv.w*v0.w;
        a1 += hv.x*v1.x + hv.y*v1.y + hv.z*v1.z + hv.w*v1.w;
        a2 += hv.x*v2.x + hv.y*v2.y + hv.z*v2.z + hv.w*v2.w;
        a3 += hv.x*v3.x + hv.y*v3.y + hv.z*v3.z + hv.w*v3.w;
    }
    #pragma unroll
    for (int off = 16; off; off >>= 1) {
        a0 += __shfl_xor_sync(0xFFFFFFFFu, a0, off);
        a1 += __shfl_xor_sync(0xFFFFFFFFu, a1, off);
        a2 += __shfl_xor_sync(0xFFFFFFFFu, a2, off);
        a3 += __shfl_xor_sync(0xFFFFFFFFu, a3, off);
    }
    if (lane == 0) { s_part[w][0]=a0; s_part[w][1]=a1; s_part[w][2]=a2; s_part[w][3]=a3; }
    __syncthreads();
    if (threadIdx.x < 8) {
        int rowin = threadIdx.x >> 2, b = threadIdx.x & 3;
        float s = s_part[rowin*4+0][b] + s_part[rowin*4+1][b]
                + s_part[rowin*4+2][b] + s_part[rowin*4+3][b];
        g_t[b*D + blockIdx.x*2 + rowin] = s;
    }
}

// ============ GEMV 2a: column-term partials: sum_{i in chunk} t[b,i]*ju[i,k] ============
// grid = (8 col-tiles of 256, ICK chunks of 16 rows) = 1024 blocks
__global__ void __launch_bounds__(256) k_col(const float* __restrict__ ju) {
    __shared__ float s_t[B][RPC];
    int ck = blockIdx.y;
    int i0 = ck*RPC;
    if (threadIdx.x < B*RPC) {
        int b = threadIdx.x >> 4, ii = threadIdx.x & 15;
        s_t[b][ii] = g_t[b*D + i0 + ii];
    }
    __syncthreads();
    int k = blockIdx.x*256 + threadIdx.x;
    float a0=0.f, a1=0.f, a2=0.f, a3=0.f;
    #pragma unroll
    for (int ii = 0; ii < RPC; ++ii) {
        float v = ju[(size_t)(i0 + ii)*D + k];
        a0 += s_t[0][ii]*v;
        a1 += s_t[1][ii]*v;
        a2 += s_t[2][ii]*v;
        a3 += s_t[3][ii]*v;
    }
    g_colpart[(size_t)(ck*B + 0)*D + k] = a0;
    g_colpart[(size_t)(ck*B + 1)*D + k] = a1;
    g_colpart[(size_t)(ck*B + 2)*D + k] = a2;
    g_colpart[(size_t)(ck*B + 3)*D + k] = a3;
}

// ============ Finalize column term ============
__global__ void k_colsum() {
    int idx = blockIdx.x*256 + threadIdx.x;   // 0..B*D-1 (layout matches colpart inner)
    float s = 0.f;
    #pragma unroll 16
    for (int c = 0; c < ICK; ++c)
        s += g_colpart[(size_t)c*B*D + idx];
    g_colsum[idx] = s;
}

// ============ GEMV 2b + finalize delta ============
// delta[b,k] = DT * ( sum_i ju[k,i]*t[b,i] - colsum[b,k] - softplus(r[k])*t[b,k] )
__global__ void __launch_bounds__(256) k_delta(const float* __restrict__ ju,
                                               const float* __restrict__ rd) {
    __shared__ float s_part[8][4];
    int w = threadIdx.x >> 5, lane = threadIdx.x & 31;
    int row = blockIdx.x*2 + (w >> 2);
    int q   = w & 3;
    const float4* jp = (const float4*)(ju + (size_t)row*D);
    const float4* t0 = (const float4*)(g_t + 0*D);
    const float4* t1 = (const float4*)(g_t + 1*D);
    const float4* t2 = (const float4*)(g_t + 2*D);
    const float4* t3 = (const float4*)(g_t + 3*D);
    float a0=0.f, a1=0.f, a2=0.f, a3=0.f;
    #pragma unroll
    for (int i = 0; i < 4; ++i) {
        int j4 = q*128 + i*32 + lane;
        float4 jv = jp[j4];
        float4 v0 = t0[j4], v1 = t1[j4], v2 = t2[j4], v3 = t3[j4];
        a0 += jv.x*v0.x + jv.y*v0.y + jv.z*v0.z + jv.w*v0.w;
        a1 += jv.x*v1.x + jv.y*v1.y + jv.z*v1.z + jv.w*v1.w;
        a2 += jv.x*v2.x + jv.y*v2.y + jv.z*v2.z + jv.w*v2.w;
        a3 += jv.x*v3.x + jv.y*v3.y + jv.z*v3.z + jv.w*v3.w;
    }
    #pragma unroll
    for (int off = 16; off; off >>= 1) {
        a0 += __shfl_xor_sync(0xFFFFFFFFu, a0, off);
        a1 += __shfl_xor_sync(0xFFFFFFFFu, a1, off);
        a2 += __shfl_xor_sync(0xFFFFFFFFu, a2, off);
        a3 += __shfl_xor_sync(0xFFFFFFFFu, a3, off);
    }
    if (lane == 0) { s_part[w][0]=a0; s_part[w][1]=a1; s_part[w][2]=a2; s_part[w][3]=a3; }
    __syncthreads();
    if (threadIdx.x < 8) {
        int rowin = threadIdx.x >> 2, b = threadIdx.x & 3;
        int k = blockIdx.x*2 + rowin;
        float rowdot = s_part[rowin*4+0][b] + s_part[rowin*4+1][b]
                     + s_part[rowin*4+2][b] + s_part[rowin*4+3][b];
        float rv = rd[k];
        float r = (rv > 20.f) ? rv : log1pf(expf(rv));   // softplus
        g_delta[b*D + k] = DT_STEP * (rowdot - g_colsum[b*D + k] - r*g_t[b*D + k]);
    }
}

// ============ Chebyshev helper ============
__device__ __forceinline__ float cheb_eval(float xn, const float* __restrict__ c) {
    float tp = 1.f, tc = xn;
    float o = fmaf(c[1], xn, c[0]);
    #pragma unroll
    for (int i = 2; i <= DEG; ++i) {
        float tn = fmaf(2.f*xn, tc, -tp);
        o = fmaf(c[i], tn, o);
        tp = tc; tc = tn;
    }
    return o;
}

// ============ Main fused pass: y=x+delta, row L2 norm, Chebyshev, out ============
__global__ void __launch_bounds__(256) k_main(const float* __restrict__ x,
                                              const float* __restrict__ coef,
                                              float* __restrict__ out) {
    __shared__ float s_delta[D];   // 8 KB
    __shared__ float s_c[DEG+1];
    __shared__ float s_red[9];
    int l = blockIdx.x, b = blockIdx.y;
    int tid = threadIdx.x;
    if (tid <= DEG) s_c[tid] = coef[tid];
    for (int i = tid; i < D/4; i += 256)
        ((float4*)s_delta)[i] = ((const float4*)&g_delta[b*D])[i];
    __syncthreads();

    size_t base = ((size_t)b*L + l)*D;
    const float4* xp = (const float4*)(x + base);
    float4*       op = (float4*)(out + base);

    float4 y0 = xp[tid];
    float4 y1 = xp[tid + 256];
    float4 d0 = ((const float4*)s_delta)[tid];
    float4 d1 = ((const float4*)s_delta)[tid + 256];
    y0.x += d0.x; y0.y += d0.y; y0.z += d0.z; y0.w += d0.w;
    y1.x += d1.x; y1.y += d1.y; y1.z += d1.z; y1.w += d1.w;

    float sq = y0.x*y0.x + y0.y*y0.y + y0.z*y0.z + y0.w*y0.w
             + y1.x*y1.x + y1.y*y1.y + y1.z*y1.z + y1.w*y1.w;
    #pragma unroll
    for (int off = 16; off; off >>= 1)
        sq += __shfl_xor_sync(0xFFFFFFFFu, sq, off);
    int warp = tid >> 5, lane = tid & 31;
    if (lane == 0) s_red[warp] = sq;
    __syncthreads();
    if (warp == 0) {
        float v = (lane < 8) ? s_red[lane] : 0.f;
        #pragma unroll
        for (int off = 4; off; off >>= 1)
            v += __shfl_xor_sync(0xFFFFFFFFu, v, off);
        if (lane == 0) s_red[8] = v;
    }
    __syncthreads();
    float inv = rsqrtf(fmaxf(s_red[8], 1e-8f));

    float4 r0, r1;
    r0.x = y0.x + 0.1f*cheb_eval(y0.x*inv, s_c);
    r0.y = y0.y + 0.1f*cheb_eval(y0.y*inv, s_c);
    r0.z = y0.z + 0.1f*cheb_eval(y0.z*inv, s_c);
    r0.w = y0.w + 0.1f*cheb_eval(y0.w*inv, s_c);
    r1.x = y1.x + 0.1f*cheb_eval(y1.x*inv, s_c);
    r1.y = y1.y + 0.1f*cheb_eval(y1.y*inv, s_c);
    r1.z = y1.z + 0.1f*cheb_eval(y1.z*inv, s_c);
    r1.w = y1.w + 0.1f*cheb_eval(y1.w*inv, s_c);
    op[tid]       = r0;
    op[tid + 256] = r1;
}

extern "C" void kernel_launch(void* const* d_in, const int* in_sizes, int n_in,
                              void* d_out, int out_size) {
    const float* x   = (const float*)d_in[0];   // [B, L, D]
    const float* ju  = (const float*)d_in[1];   // [D, D]
    const float* rd  = (const float*)d_in[2];   // [D]
    const float* hp  = (const float*)d_in[3];   // [D, D]
    const float* cf  = (const float*)d_in[4];   // [9]
    float* out = (float*)d_out;
    (void)in_sizes; (void)n_in; (void)out_size;

    k_partial<<<dim3(2, LC, B), 256>>>(x);
    k_mean<<<(B*D)/256, 256>>>();
    k_gemv1<<<D/2, 256>>>(hp);
    k_col<<<dim3(8, ICK), 256>>>(ju);
    k_colsum<<<(B*D)/256, 256>>>();
    k_delta<<<D/2, 256>>>(ju, rd);
    k_main<<<dim3(L, B), 256>>>(x, cf, out);
}

// round 4
// speedup vs baseline: 1.2644x; 1.2644x over previous
#include <cuda_runtime.h>
#include <math.h>

#define B 4
#define L 2048
#define D 2048
#define NBLK 512       // persistent-kernel grid (must be <= 148*4 for residency)
#define LC 64          // partial-mean chunks
#define ICK 64         // col-term i-chunks (32 rows each)
#define DT_STEP 0.01f
#define DEG 8

// ---- scratch (device globals, no allocation allowed) ----
__device__ float g_partial[B*LC*D];    // 2 MB
__device__ float g_xmean[B*D];         // 32 KB
__device__ float g_t[B*D];             // 32 KB  t = H @ x_mean
__device__ float g_colpart[ICK*B*D];   // 2 MB
__device__ float g_delta[B*D];         // 32 KB

// ---- grid barrier (generation-based: replay-safe, never reset gen) ----
__device__ unsigned g_bar_count = 0;
__device__ unsigned g_bar_gen   = 0;

__device__ __forceinline__ void gridbar() {
    __syncthreads();
    if (threadIdx.x == 0) {
        __threadfence();
        unsigned gen = *(volatile unsigned*)&g_bar_gen;
        unsigned old = atomicAdd(&g_bar_count, 1u);
        if (old == NBLK - 1) {
            g_bar_count = 0;
            __threadfence();
            *(volatile unsigned*)&g_bar_gen = gen + 1;
        } else {
            while (*(volatile unsigned*)&g_bar_gen == gen) { __nanosleep(32); }
        }
        __threadfence();
    }
    __syncthreads();
}

// ============ Fused mid chain: partial -> mean -> gemv1 -> colpart -> delta ============
__global__ void __launch_bounds__(256, 4) k_mid(const float* __restrict__ x,
                                                const float* __restrict__ ju,
                                                const float* __restrict__ hp,
                                                const float* __restrict__ rd) {
    __shared__ float s_t[B][32];
    __shared__ float s_part[8][4];
    const int bid = blockIdx.x;
    const int t   = threadIdx.x;
    const int w = t >> 5, lane = t & 31;

    // ---------- P0: partial column sums of x over L ----------
    {
        int b     = bid >> 7;          // 4
        int rem   = bid & 127;
        int lc32  = rem >> 2;          // 32
        int dtile = rem & 3;           // 4 tiles of 512 floats
        int k4    = t & 127;           // float4 within 512-float tile
        int lr    = t >> 7;            // 2 row-groups of 32
        int dcol  = dtile*512 + k4*4;
        int l0    = lc32*64 + lr*32;
        const float4* xp = (const float4*)x;
        float4 acc = make_float4(0.f,0.f,0.f,0.f);
        size_t base = (((size_t)b*L + l0)*D + dcol) >> 2;
        #pragma unroll
        for (int s = 0; s < 32; ++s) {
            float4 v = xp[base + (size_t)s*(D/4)];
            acc.x += v.x; acc.y += v.y; acc.z += v.z; acc.w += v.w;
        }
        *(float4*)&g_partial[(size_t)(b*LC + lc32*2 + lr)*D + dcol] = acc;
    }
    gridbar();

    // ---------- P1: finalize mean (32 blocks) ----------
    if (bid < 32) {
        int idx = bid*256 + t;          // 0..8191
        int b = idx >> 11, d = idx & (D-1);
        float s = 0.f;
        #pragma unroll 16
        for (int c = 0; c < LC; ++c)
            s += g_partial[(size_t)(b*LC + c)*D + d];
        g_xmean[idx] = s * (1.0f/(float)L);
    }
    gridbar();

    // ---------- P2: t[b,i] = sum_j hp[i,j]*xmean[b,j]  (4 rows/block, 2 warps/row) ----------
    {
        int row  = bid*4 + (w >> 1);
        int half = w & 1;
        const float4* hr = (const float4*)(hp + (size_t)row*D);
        const float4* m0 = (const float4*)(g_xmean + 0*D);
        const float4* m1 = (const float4*)(g_xmean + 1*D);
        const float4* m2 = (const float4*)(g_xmean + 2*D);
        const float4* m3 = (const float4*)(g_xmean + 3*D);
        float a0=0.f,a1=0.f,a2=0.f,a3=0.f;
        #pragma unroll
        for (int it = 0; it < 8; ++it) {
            int j4 = half*256 + it*32 + lane;
            float4 hv = hr[j4];
            float4 v0 = m0[j4], v1 = m1[j4], v2 = m2[j4], v3 = m3[j4];
            a0 += hv.x*v0.x + hv.y*v0.y + hv.z*v0.z + hv.w*v0.w;
            a1 += hv.x*v1.x + hv.y*v1.y + hv.z*v1.z + hv.w*v1.w;
            a2 += hv.x*v2.x + hv.y*v2.y + hv.z*v2.z + hv.w*v2.w;
            a3 += hv.x*v3.x + hv.y*v3.y + hv.z*v3.z + hv.w*v3.w;
        }
        #pragma unroll
        for (int off = 16; off; off >>= 1) {
            a0 += __shfl_xor_sync(0xFFFFFFFFu, a0, off);
            a1 += __shfl_xor_sync(0xFFFFFFFFu, a1, off);
            a2 += __shfl_xor_sync(0xFFFFFFFFu, a2, off);
            a3 += __shfl_xor_sync(0xFFFFFFFFu, a3, off);
        }
        if (lane == 0) { s_part[w][0]=a0; s_part[w][1]=a1; s_part[w][2]=a2; s_part[w][3]=a3; }
        __syncthreads();
        if (t < 16) {
            int rowin = t >> 2, b = t & 3;
            float s = s_part[rowin*2][b] + s_part[rowin*2+1][b];
            g_t[b*D + bid*4 + rowin] = s;
        }
    }
    gridbar();

    // ---------- P3: col partials: sum_{i in chunk} t[b,i]*ju[i,k] ----------
    {
        int ktile = bid >> 6;      // 8 tiles of 256 cols
        int ick   = bid & 63;      // 64 chunks of 32 rows
        int i0    = ick*32;
        if (t < B*32) {
            int b = t >> 5, ii = t & 31;
            s_t[b][ii] = g_t[b*D + i0 + ii];
        }
        __syncthreads();
        int k = ktile*256 + t;
        float a0=0.f,a1=0.f,a2=0.f,a3=0.f;
        #pragma unroll
        for (int ii = 0; ii < 32; ++ii) {
            float v = ju[(size_t)(i0+ii)*D + k];
            a0 += s_t[0][ii]*v;
            a1 += s_t[1][ii]*v;
            a2 += s_t[2][ii]*v;
            a3 += s_t[3][ii]*v;
        }
        g_colpart[(size_t)(ick*B + 0)*D + k] = a0;
        g_colpart[(size_t)(ick*B + 1)*D + k] = a1;
        g_colpart[(size_t)(ick*B + 2)*D + k] = a2;
        g_colpart[(size_t)(ick*B + 3)*D + k] = a3;
    }
    gridbar();

    // ---------- P4: row dots + finalize delta ----------
    {
        int row  = bid*4 + (w >> 1);
        int half = w & 1;
        const float4* jr = (const float4*)(ju + (size_t)row*D);
        const float4* t0 = (const float4*)(g_t + 0*D);
        const float4* t1 = (const float4*)(g_t + 1*D);
        const float4* t2 = (const float4*)(g_t + 2*D);
        const float4* t3 = (const float4*)(g_t + 3*D);
        float a0=0.f,a1=0.f,a2=0.f,a3=0.f;
        #pragma unroll
        for (int it = 0; it < 8; ++it) {
            int j4 = half*256 + it*32 + lane;
            float4 jv = jr[j4];
            float4 v0 = t0[j4], v1 = t1[j4], v2 = t2[j4], v3 = t3[j4];
            a0 += jv.x*v0.x + jv.y*v0.y + jv.z*v0.z + jv.w*v0.w;
            a1 += jv.x*v1.x + jv.y*v1.y + jv.z*v1.z + jv.w*v1.w;
            a2 += jv.x*v2.x + jv.y*v2.y + jv.z*v2.z + jv.w*v2.w;
            a3 += jv.x*v3.x + jv.y*v3.y + jv.z*v3.z + jv.w*v3.w;
        }
        #pragma unroll
        for (int off = 16; off; off >>= 1) {
            a0 += __shfl_xor_sync(0xFFFFFFFFu, a0, off);
            a1 += __shfl_xor_sync(0xFFFFFFFFu, a1, off);
            a2 += __shfl_xor_sync(0xFFFFFFFFu, a2, off);
            a3 += __shfl_xor_sync(0xFFFFFFFFu, a3, off);
        }
        __syncthreads();   // protect s_part reuse
        if (lane == 0) { s_part[w][0]=a0; s_part[w][1]=a1; s_part[w][2]=a2; s_part[w][3]=a3; }
        __syncthreads();
        if (t < 16) {
            int rowin = t >> 2, b = t & 3;
            int k = bid*4 + rowin;
            float rowdot = s_part[rowin*2][b] + s_part[rowin*2+1][b];
            float col = 0.f;
            #pragma unroll 16
            for (int c = 0; c < ICK; ++c)
                col += g_colpart[(size_t)(c*B + b)*D + k];
            float rv = rd[k];
            float r = (rv > 20.f) ? rv : log1pf(expf(rv));
            g_delta[b*D + k] = DT_STEP * (rowdot - col - r*g_t[b*D + k]);
        }
    }
}

// ============ Chebyshev helper ============
__device__ __forceinline__ float cheb_eval(float xn, const float* __restrict__ c) {
    float tp = 1.f, tc = xn;
    float o = fmaf(c[1], xn, c[0]);
    #pragma unroll
    for (int i = 2; i <= DEG; ++i) {
        float tn = fmaf(2.f*xn, tc, -tp);
        o = fmaf(c[i], tn, o);
        tp = tc; tc = tn;
    }
    return o;
}

// ============ Main fused pass ============
__global__ void __launch_bounds__(256) k_main(const float* __restrict__ x,
                                              const float* __restrict__ coef,
                                              float* __restrict__ out) {
    __shared__ float s_red[9];
    int l = blockIdx.x, b = blockIdx.y;
    int tid = threadIdx.x;

    size_t base = ((size_t)b*L + l)*D;
    const float4* xp = (const float4*)(x + base);
    float4*       op = (float4*)(out + base);
    const float4* dp = (const float4*)(g_delta + b*D);

    float4 y0 = xp[tid];
    float4 y1 = xp[tid + 256];
    float4 d0 = dp[tid];
    float4 d1 = dp[tid + 256];
    y0.x += d0.x; y0.y += d0.y; y0.z += d0.z; y0.w += d0.w;
    y1.x += d1.x; y1.y += d1.y; y1.z += d1.z; y1.w += d1.w;

    float sq = y0.x*y0.x + y0.y*y0.y + y0.z*y0.z + y0.w*y0.w
             + y1.x*y1.x + y1.y*y1.y + y1.z*y1.z + y1.w*y1.w;
    #pragma unroll
    for (int off = 16; off; off >>= 1)
        sq += __shfl_xor_sync(0xFFFFFFFFu, sq, off);
    int warp = tid >> 5, lane = tid & 31;
    if (lane == 0) s_red[warp] = sq;
    __syncthreads();
    if (warp == 0) {
        float v = (lane < 8) ? s_red[lane] : 0.f;
        #pragma unroll
        for (int off = 4; off; off >>= 1)
            v += __shfl_xor_sync(0xFFFFFFFFu, v, off);
        if (lane == 0) s_red[8] = v;
    }
    __syncthreads();
    float inv = rsqrtf(fmaxf(s_red[8], 1e-8f));

    float c[DEG+1];
    #pragma unroll
    for (int i = 0; i <= DEG; ++i) c[i] = __ldg(&coef[i]);

    float4 r0, r1;
    r0.x = y0.x + 0.1f*cheb_eval(y0.x*inv, c);
    r0.y = y0.y + 0.1f*cheb_eval(y0.y*inv, c);
    r0.z = y0.z + 0.1f*cheb_eval(y0.z*inv, c);
    r0.w = y0.w + 0.1f*cheb_eval(y0.w*inv, c);
    r1.x = y1.x + 0.1f*cheb_eval(y1.x*inv, c);
    r1.y = y1.y + 0.1f*cheb_eval(y1.y*inv, c);
    r1.z = y1.z + 0.1f*cheb_eval(y1.z*inv, c);
    r1.w = y1.w + 0.1f*cheb_eval(y1.w*inv, c);
    op[tid]       = r0;
    op[tid + 256] = r1;
}

extern "C" void kernel_launch(void* const* d_in, const int* in_sizes, int n_in,
                              void* d_out, int out_size) {
    const float* x   = (const float*)d_in[0];   // [B, L, D]
    const float* ju  = (const float*)d_in[1];   // [D, D]
    const float* rd  = (const float*)d_in[2];   // [D]
    const float* hp  = (const float*)d_in[3];   // [D, D]
    const float* cf  = (const float*)d_in[4];   // [9]
    float* out = (float*)d_out;
    (void)in_sizes; (void)n_in; (void)out_size;

    k_mid<<<NBLK, 256>>>(x, ju, hp, rd);
    k_main<<<dim3(L, B), 256>>>(x, cf, out);
}

// round 6
// speedup vs baseline: 1.3244x; 1.0474x over previous
#include <cuda_runtime.h>
#include <math.h>

#define B 4
#define L 2048
#define D 2048
#define NBLK 512       // persistent-kernel grid (<= 148*4 for residency)
#define LC 64          // partial-mean chunks
#define ICK 64         // col-term i-chunks (32 rows each)
#define DT_STEP 0.01f
#define DEG 8

// ---- scratch (device globals, no allocation allowed) ----
__device__ float g_partial[B*LC*D];    // 2 MB
__device__ float g_xmean[B*D];         // 32 KB
__device__ float g_t[B*D];             // 32 KB
__device__ float g_colpart[ICK*B*D];   // 2 MB
__device__ float g_delta[B*D];         // 32 KB
__device__ float g_mono[DEG+1];        // monomial coeffs of sum c_i T_i

// ---- grid barrier (generation-based: replay-safe, never reset gen) ----
__device__ unsigned g_bar_count = 0;
__device__ unsigned g_bar_gen   = 0;

__device__ __forceinline__ void gridbar() {
    __syncthreads();
    if (threadIdx.x == 0) {
        __threadfence();
        unsigned gen = *(volatile unsigned*)&g_bar_gen;
        unsigned old = atomicAdd(&g_bar_count, 1u);
        if (old == NBLK - 1) {
            g_bar_count = 0;
            __threadfence();
            *(volatile unsigned*)&g_bar_gen = gen + 1;
        } else {
            while (*(volatile unsigned*)&g_bar_gen == gen) {}
        }
        __threadfence();
    }
    __syncthreads();
}

// ============ Fused mid chain ============
__global__ void __launch_bounds__(256, 4) k_mid(const float* __restrict__ x,
                                                const float* __restrict__ ju,
                                                const float* __restrict__ hp,
                                                const float* __restrict__ rd,
                                                const float* __restrict__ cf) {
    __shared__ float s_t[B][32];
    __shared__ float s_part[8][4];
    __shared__ float s_col[16][17];
    const int bid = blockIdx.x;
    const int t   = threadIdx.x;
    const int w = t >> 5, lane = t & 31;

    // ---------- one-time: Chebyshev -> monomial coefficient conversion ----------
    if (bid == NBLK-1 && t == 0) {
        float tp[9], tc[9], tn[9], m[9];
        #pragma unroll
        for (int i = 0; i < 9; ++i) { tp[i]=0.f; tc[i]=0.f; m[i]=0.f; }
        tp[0] = 1.f;              // T0
        tc[1] = 1.f;              // T1
        m[0] = cf[0];
        m[1] = cf[1];
        for (int n = 2; n <= DEG; ++n) {
            for (int i = 0; i < 9; ++i)
                tn[i] = (i ? 2.f*tc[i-1] : 0.f) - tp[i];
            float c = cf[n];
            for (int i = 0; i < 9; ++i) m[i] += c*tn[i];
            for (int i = 0; i < 9; ++i) { tp[i]=tc[i]; tc[i]=tn[i]; }
        }
        for (int i = 0; i < 9; ++i) g_mono[i] = m[i];
    }

    // ---------- P0: partial column sums of x over L ----------
    {
        int b     = bid >> 7;
        int rem   = bid & 127;
        int lc32  = rem >> 2;
        int dtile = rem & 3;
        int k4    = t & 127;
        int lr    = t >> 7;
        int dcol  = dtile*512 + k4*4;
        int l0    = lc32*64 + lr*32;
        const float4* xp = (const float4*)x;
        float4 acc = make_float4(0.f,0.f,0.f,0.f);
        size_t base = (((size_t)b*L + l0)*D + dcol) >> 2;
        #pragma unroll
        for (int s = 0; s < 32; ++s) {
            float4 v = xp[base + (size_t)s*(D/4)];
            acc.x += v.x; acc.y += v.y; acc.z += v.z; acc.w += v.w;
        }
        *(float4*)&g_partial[(size_t)(b*LC + lc32*2 + lr)*D + dcol] = acc;
    }
    gridbar();

    // ---------- P1: finalize mean (32 blocks) ----------
    if (bid < 32) {
        int idx = bid*256 + t;
        int b = idx >> 11, d = idx & (D-1);
        float s = 0.f;
        #pragma unroll 16
        for (int c = 0; c < LC; ++c)
            s += g_partial[(size_t)(b*LC + c)*D + d];
        g_xmean[idx] = s * (1.0f/(float)L);
    }
    gridbar();

    // ---------- P2: t[b,i] = sum_j hp[i,j]*xmean[b,j]  (4 rows/block, 2 warps/row) ----------
    {
        int row  = bid*4 + (w >> 1);
        int half = w & 1;
        const float4* hr = (const float4*)(hp + (size_t)row*D);
        const float4* m0 = (const float4*)(g_xmean + 0*D);
        const float4* m1 = (const float4*)(g_xmean + 1*D);
        const float4* m2 = (const float4*)(g_xmean + 2*D);
        const float4* m3 = (const float4*)(g_xmean + 3*D);
        float a0=0.f,a1=0.f,a2=0.f,a3=0.f;
        #pragma unroll
        for (int it = 0; it < 8; ++it) {
            int j4 = half*256 + it*32 + lane;
            float4 hv = hr[j4];
            float4 v0 = m0[j4], v1 = m1[j4], v2 = m2[j4], v3 = m3[j4];
            a0 += hv.x*v0.x + hv.y*v0.y + hv.z*v0.z + hv.w*v0.w;
            a1 += hv.x*v1.x + hv.y*v1.y + hv.z*v1.z + hv.w*v1.w;
            a2 += hv.x*v2.x + hv.y*v2.y + hv.z*v2.z + hv.w*v2.w;
            a3 += hv.x*v3.x + hv.y*v3.y + hv.z*v3.z + hv.w*v3.w;
        }
        #pragma unroll
        for (int off = 16; off; off >>= 1) {
            a0 += __shfl_xor_sync(0xFFFFFFFFu, a0, off);
            a1 += __shfl_xor_sync(0xFFFFFFFFu, a1, off);
            a2 += __shfl_xor_sync(0xFFFFFFFFu, a2, off);
            a3 += __shfl_xor_sync(0xFFFFFFFFu, a3, off);
        }
        if (lane == 0) { s_part[w][0]=a0; s_part[w][1]=a1; s_part[w][2]=a2; s_part[w][3]=a3; }
        __syncthreads();
        if (t < 16) {
            int rowin = t >> 2, b = t & 3;
            float s = s_part[rowin*2][b] + s_part[rowin*2+1][b];
            g_t[b*D + bid*4 + rowin] = s;
        }
    }
    gridbar();

    // ---------- P3: col partials: sum_{i in chunk} t[b,i]*ju[i,k] ----------
    {
        int ktile = bid >> 6;
        int ick   = bid & 63;
        int i0    = ick*32;
        if (t < B*32) {
            int b = t >> 5, ii = t & 31;
            s_t[b][ii] = g_t[b*D + i0 + ii];
        }
        __syncthreads();
        int k = ktile*256 + t;
        float a0=0.f,a1=0.f,a2=0.f,a3=0.f;
        #pragma unroll
        for (int ii = 0; ii < 32; ++ii) {
            float v = ju[(size_t)(i0+ii)*D + k];
            a0 += s_t[0][ii]*v;
            a1 += s_t[1][ii]*v;
            a2 += s_t[2][ii]*v;
            a3 += s_t[3][ii]*v;
        }
        g_colpart[(size_t)(ick*B + 0)*D + k] = a0;
        g_colpart[(size_t)(ick*B + 1)*D + k] = a1;
        g_colpart[(size_t)(ick*B + 2)*D + k] = a2;
        g_colpart[(size_t)(ick*B + 3)*D + k] = a3;
    }
    gridbar();

    // ---------- P4: row dots + parallel col-sum + finalize delta ----------
    {
        int row  = bid*4 + (w >> 1);
        int half = w & 1;
        const float4* jr = (const float4*)(ju + (size_t)row*D);
        const float4* t0 = (const float4*)(g_t + 0*D);
        const float4* t1 = (const float4*)(g_t + 1*D);
        const float4* t2 = (const float4*)(g_t + 2*D);
        const float4* t3 = (const float4*)(g_t + 3*D);
        float a0=0.f,a1=0.f,a2=0.f,a3=0.f;
        #pragma unroll
        for (int it = 0; it < 8; ++it) {
            int j4 = half*256 + it*32 + lane;
            float4 jv = jr[j4];
            float4 v0 = t0[j4], v1 = t1[j4], v2 = t2[j4], v3 = t3[j4];
            a0 += jv.x*v0.x + jv.y*v0.y + jv.z*v0.z + jv.w*v0.w;
            a1 += jv.x*v1.x + jv.y*v1.y + jv.z*v1.z + jv.w*v1.w;
            a2 += jv.x*v2.x + jv.y*v2.y + jv.z*v2.z + jv.w*v2.w;
            a3 += jv.x*v3.x + jv.y*v3.y + jv.z*v3.z + jv.w*v3.w;
        }
        #pragma unroll
        for (int off = 16; off; off >>= 1) {
            a0 += __shfl_xor_sync(0xFFFFFFFFu, a0, off);
            a1 += __shfl_xor_sync(0xFFFFFFFFu, a1, off);
            a2 += __shfl_xor_sync(0xFFFFFFFFu, a2, off);
            a3 += __shfl_xor_sync(0xFFFFFFFFu, a3, off);
        }
        if (lane == 0) { s_part[w][0]=a0; s_part[w][1]=a1; s_part[w][2]=a2; s_part[w][3]=a3; }

        // parallel colpart reduction: pair p = (rowin<<2)|b handled by 16 threads
        {
            int p = t >> 4;          // 0..15
            int g = t & 15;          // 0..15 (chunk group of 4)
            int b = p & 3, rowin = p >> 2;
            int k = bid*4 + rowin;
            float s = 0.f;
            #pragma unroll
            for (int c = 0; c < 4; ++c)
                s += g_colpart[(size_t)((g*4+c)*B + b)*D + k];
            s_col[p][g] = s;
        }
        __syncthreads();
        if (t < 16) {
            int rowin = t >> 2, b = t & 3;
            int k = bid*4 + rowin;
            float rowdot = s_part[rowin*2][b] + s_part[rowin*2+1][b];
            float col = 0.f;
            #pragma unroll
            for (int g = 0; g < 16; ++g) col += s_col[t][g];
            float rv = rd[k];
            float r = (rv > 20.f) ? rv : log1pf(expf(rv));
            g_delta[b*D + k] = DT_STEP * (rowdot - col - r*g_t[b*D + k]);
        }
    }
}

// ============ degree-8 polynomial via even/odd Horner ============
__device__ __forceinline__ float poly_eval(float xn, const float* __restrict__ m) {
    float u  = xn*xn;
    float pe = fmaf(fmaf(fmaf(fmaf(m[8],u,m[6]),u,m[4]),u,m[2]),u,m[0]);
    float po = fmaf(fmaf(fmaf(m[7],u,m[5]),u,m[3]),u,m[1]);
    return fmaf(xn, po, pe);
}

// ============ Main fused pass ============
__global__ void __launch_bounds__(256) k_main(const float* __restrict__ x,
                                              float* __restrict__ out) {
    __shared__ float s_red[9];
    int l = blockIdx.x, b = blockIdx.y;
    int tid = threadIdx.x;

    size_t base = ((size_t)b*L + l)*D;
    const float4* xp = (const float4*)(x + base);
    float4*       op = (float4*)(out + base);
    const float4* dp = (const float4*)(g_delta + b*D);

    float4 y0 = xp[tid];
    float4 y1 = xp[tid + 256];
    float4 d0 = dp[tid];
    float4 d1 = dp[tid + 256];
    y0.x += d0.x; y0.y += d0.y; y0.z += d0.z; y0.w += d0.w;
    y1.x += d1.x; y1.y += d1.y; y1.z += d1.z; y1.w += d1.w;

    float sq = y0.x*y0.x + y0.y*y0.y + y0.z*y0.z + y0.w*y0.w
             + y1.x*y1.x + y1.y*y1.y + y1.z*y1.z + y1.w*y1.w;
    #pragma unroll
    for (int off = 16; off; off >>= 1)
        sq += __shfl_xor_sync(0xFFFFFFFFu, sq, off);
    int warp = tid >> 5, lane = tid & 31;
    if (lane == 0) s_red[warp] = sq;
    __syncthreads();
    if (warp == 0) {
        float v = (lane < 8) ? s_red[lane] : 0.f;
        #pragma unroll
        for (int off = 4; off; off >>= 1)
            v += __shfl_xor_sync(0xFFFFFFFFu, v, off);
        if (lane == 0) s_red[8] = v;
    }
    __syncthreads();
    float inv = rsqrtf(fmaxf(s_red[8], 1e-8f));

    float m[DEG+1];
    #pragma unroll
    for (int i = 0; i <= DEG; ++i) m[i] = g_mono[i];

    float4 r0, r1;
    r0.x = y0.x + 0.1f*poly_eval(y0.x*inv, m);
    r0.y = y0.y + 0.1f*poly_eval(y0.y*inv, m);
    r0.z = y0.z + 0.1f*poly_eval(y0.z*inv, m);
    r0.w = y0.w + 0.1f*poly_eval(y0.w*inv, m);
    r1.x = y1.x + 0.1f*poly_eval(y1.x*inv, m);
    r1.y = y1.y + 0.1f*poly_eval(y1.y*inv, m);
    r1.z = y1.z + 0.1f*poly_eval(y1.z*inv, m);
    r1.w = y1.w + 0.1f*poly_eval(y1.w*inv, m);
    op[tid]       = r0;
    op[tid + 256] = r1;
}

extern "C" void kernel_launch(void* const* d_in, const int* in_sizes, int n_in,
                              void* d_out, int out_size) {
    const float* x   = (const float*)d_in[0];   // [B, L, D]
    const float* ju  = (const float*)d_in[1];   // [D, D]
    const float* rd  = (const float*)d_in[2];   // [D]
    const float* hp  = (const float*)d_in[3];   // [D, D]
    const float* cf  = (const float*)d_in[4];   // [9]
    float* out = (float*)d_out;
    (void)in_sizes; (void)n_in; (void)out_size;

    k_mid<<<NBLK, 256>>>(x, ju, hp, rd, cf);
    k_main<<<dim3(L, B), 256>>>(x, out);
}

// round 7
// speedup vs baseline: 1.3778x; 1.0404x over previous
#include <cuda_runtime.h>
#include <math.h>

#define B 4
#define L 2048
#define D 2048
#define NBLK 512       // persistent-kernel grid (<= 148*4 for residency)
#define ICK 64         // col-term i-chunks (32 rows each)
#define DT_STEP 0.01f
#define DEG 8

// ---- scratch (device globals, no allocation allowed) ----
__device__ float g_xmean[B*D];         // 32 KB
__device__ float g_t[B*D];             // 32 KB
__device__ float g_colpart[ICK*B*D];   // 2 MB
__device__ float g_delta[B*D];         // 32 KB
__device__ float g_mono[DEG+1];        // monomial coeffs of sum c_i T_i

// ---- grid barrier (generation-based: replay-safe, never reset gen) ----
__device__ unsigned g_bar_count = 0;
__device__ unsigned g_bar_gen   = 0;

__device__ __forceinline__ void gridbar() {
    __syncthreads();
    if (threadIdx.x == 0) {
        __threadfence();
        unsigned gen = *(volatile unsigned*)&g_bar_gen;
        unsigned old = atomicAdd(&g_bar_count, 1u);
        if (old == NBLK - 1) {
            g_bar_count = 0;
            __threadfence();
            *(volatile unsigned*)&g_bar_gen = gen + 1;
        } else {
            while (*(volatile unsigned*)&g_bar_gen == gen) {}
        }
        __threadfence();
    }
    __syncthreads();
}

// ============ Fused mid chain ============
__global__ void __launch_bounds__(256, 4) k_mid(const float* __restrict__ x,
                                                const float* __restrict__ ju,
                                                const float* __restrict__ hp,
                                                const float* __restrict__ rd,
                                                const float* __restrict__ cf) {
    __shared__ float s_t[B][32];
    __shared__ float s_part[8][4];
    __shared__ float s_col[16][17];
    __shared__ float4 s_w[8][4];
    const int bid = blockIdx.x;
    const int t   = threadIdx.x;
    const int w = t >> 5, lane = t & 31;

    // ---------- one-time: Chebyshev -> monomial coefficient conversion ----------
    if (bid == NBLK-1 && t == 32) {
        float tp[9], tc[9], tn[9], m[9];
        #pragma unroll
        for (int i = 0; i < 9; ++i) { tp[i]=0.f; tc[i]=0.f; m[i]=0.f; }
        tp[0] = 1.f;              // T0
        tc[1] = 1.f;              // T1
        m[0] = cf[0];
        m[1] = cf[1];
        for (int n = 2; n <= DEG; ++n) {
            for (int i = 0; i < 9; ++i)
                tn[i] = (i ? 2.f*tc[i-1] : 0.f) - tp[i];
            float c = cf[n];
            for (int i = 0; i < 9; ++i) m[i] += c*tn[i];
            for (int i = 0; i < 9; ++i) { tp[i]=tc[i]; tc[i]=tn[i]; }
        }
        for (int i = 0; i < 9; ++i) g_mono[i] = m[i];
    }

    // ---------- P0: full-L column mean, one (b, 16-col) slab per block ----------
    {
        int b    = bid >> 7;           // 0..3
        int dcol = (bid & 127) * 16;   // 16-float slab
        int lsub = t >> 2;             // 0..63
        int c4   = t & 3;              // float4 within slab
        const float4* xp = (const float4*)x;
        size_t base = (((size_t)b*L + lsub)*D + dcol + c4*4) >> 2;
        float4 acc = make_float4(0.f,0.f,0.f,0.f);
        #pragma unroll
        for (int it = 0; it < 32; ++it) {
            float4 v = xp[base + (size_t)it*64*(D/4)];
            acc.x += v.x; acc.y += v.y; acc.z += v.z; acc.w += v.w;
        }
        // reduce over lsub bits inside warp (lane bits 2..4)
        #pragma unroll
        for (int off = 4; off <= 16; off <<= 1) {
            acc.x += __shfl_xor_sync(0xFFFFFFFFu, acc.x, off);
            acc.y += __shfl_xor_sync(0xFFFFFFFFu, acc.y, off);
            acc.z += __shfl_xor_sync(0xFFFFFFFFu, acc.z, off);
            acc.w += __shfl_xor_sync(0xFFFFFFFFu, acc.w, off);
        }
        if (lane < 4) s_w[w][lane] = acc;
        __syncthreads();
        if (t < 4) {
            float4 s = make_float4(0.f,0.f,0.f,0.f);
            #pragma unroll
            for (int ww = 0; ww < 8; ++ww) {
                float4 v = s_w[ww][t];
                s.x += v.x; s.y += v.y; s.z += v.z; s.w += v.w;
            }
            const float inv = 1.0f/(float)L;
            s.x *= inv; s.y *= inv; s.z *= inv; s.w *= inv;
            *(float4*)&g_xmean[b*D + dcol + t*4] = s;
        }
    }
    gridbar();

    // ---------- P2: t[b,i] = sum_j hp[i,j]*xmean[b,j]  (4 rows/block, 2 warps/row) ----------
    {
        int row  = bid*4 + (w >> 1);
        int half = w & 1;
        const float4* hr = (const float4*)(hp + (size_t)row*D);
        const float4* m0 = (const float4*)(g_xmean + 0*D);
        const float4* m1 = (const float4*)(g_xmean + 1*D);
        const float4* m2 = (const float4*)(g_xmean + 2*D);
        const float4* m3 = (const float4*)(g_xmean + 3*D);
        float a0=0.f,a1=0.f,a2=0.f,a3=0.f;
        #pragma unroll
        for (int it = 0; it < 8; ++it) {
            int j4 = half*256 + it*32 + lane;
            float4 hv = __ldcs(&hr[j4]);    // streaming: don't evict x from L2
            float4 v0 = m0[j4], v1 = m1[j4], v2 = m2[j4], v3 = m3[j4];
            a0 += hv.x*v0.x + hv.y*v0.y + hv.z*v0.z + hv.w*v0.w;
            a1 += hv.x*v1.x + hv.y*v1.y + hv.z*v1.z + hv.w*v1.w;
            a2 += hv.x*v2.x + hv.y*v2.y + hv.z*v2.z + hv.w*v2.w;
            a3 += hv.x*v3.x + hv.y*v3.y + hv.z*v3.z + hv.w*v3.w;
        }
        #pragma unroll
        for (int off = 16; off; off >>= 1) {
            a0 += __shfl_xor_sync(0xFFFFFFFFu, a0, off);
            a1 += __shfl_xor_sync(0xFFFFFFFFu, a1, off);
            a2 += __shfl_xor_sync(0xFFFFFFFFu, a2, off);
            a3 += __shfl_xor_sync(0xFFFFFFFFu, a3, off);
        }
        if (lane == 0) { s_part[w][0]=a0; s_part[w][1]=a1; s_part[w][2]=a2; s_part[w][3]=a3; }
        __syncthreads();
        if (t < 16) {
            int rowin = t >> 2, b = t & 3;
            float s = s_part[rowin*2][b] + s_part[rowin*2+1][b];
            g_t[b*D + bid*4 + rowin] = s;
        }
    }
    gridbar();

    // ---------- P3: col partials: sum_{i in chunk} t[b,i]*ju[i,k] ----------
    {
        int ktile = bid >> 6;
        int ick   = bid & 63;
        int i0    = ick*32;
        if (t < B*32) {
            int b = t >> 5, ii = t & 31;
            s_t[b][ii] = g_t[b*D + i0 + ii];
        }
        __syncthreads();
        int k = ktile*256 + t;
        float a0=0.f,a1=0.f,a2=0.f,a3=0.f;
        #pragma unroll
        for (int ii = 0; ii < 32; ++ii) {
            float v = __ldcs(&ju[(size_t)(i0+ii)*D + k]);
            a0 += s_t[0][ii]*v;
            a1 += s_t[1][ii]*v;
            a2 += s_t[2][ii]*v;
            a3 += s_t[3][ii]*v;
        }
        g_colpart[(size_t)(ick*B + 0)*D + k] = a0;
        g_colpart[(size_t)(ick*B + 1)*D + k] = a1;
        g_colpart[(size_t)(ick*B + 2)*D + k] = a2;
        g_colpart[(size_t)(ick*B + 3)*D + k] = a3;
    }
    gridbar();

    // ---------- P4: row dots + parallel col-sum + finalize delta ----------
    {
        int row  = bid*4 + (w >> 1);
        int half = w & 1;
        const float4* jr = (const float4*)(ju + (size_t)row*D);
        const float4* t0 = (const float4*)(g_t + 0*D);
        const float4* t1 = (const float4*)(g_t + 1*D);
        const float4* t2 = (const float4*)(g_t + 2*D);
        const float4* t3 = (const float4*)(g_t + 3*D);
        float a0=0.f,a1=0.f,a2=0.f,a3=0.f;
        #pragma unroll
        for (int it = 0; it < 8; ++it) {
            int j4 = half*256 + it*32 + lane;
            float4 jv = __ldcs(&jr[j4]);
            float4 v0 = t0[j4], v1 = t1[j4], v2 = t2[j4], v3 = t3[j4];
            a0 += jv.x*v0.x + jv.y*v0.y + jv.z*v0.z + jv.w*v0.w;
            a1 += jv.x*v1.x + jv.y*v1.y + jv.z*v1.z + jv.w*v1.w;
            a2 += jv.x*v2.x + jv.y*v2.y + jv.z*v2.z + jv.w*v2.w;
            a3 += jv.x*v3.x + jv.y*v3.y + jv.z*v3.z + jv.w*v3.w;
        }
        #pragma unroll
        for (int off = 16; off; off >>= 1) {
            a0 += __shfl_xor_sync(0xFFFFFFFFu, a0, off);
            a1 += __shfl_xor_sync(0xFFFFFFFFu, a1, off);
            a2 += __shfl_xor_sync(0xFFFFFFFFu, a2, off);
            a3 += __shfl_xor_sync(0xFFFFFFFFu, a3, off);
        }
        if (lane == 0) { s_part[w][0]=a0; s_part[w][1]=a1; s_part[w][2]=a2; s_part[w][3]=a3; }

        // parallel colpart reduction
        {
            int p = t >> 4;          // 0..15 pair (rowin<<2)|b
            int g = t & 15;          // chunk group of 4
            int b = p & 3, rowin = p >> 2;
            int k = bid*4 + rowin;
            float s = 0.f;
            #pragma unroll
            for (int c = 0; c < 4; ++c)
                s += g_colpart[(size_t)((g*4+c)*B + b)*D + k];
            s_col[p][g] = s;
        }
        __syncthreads();
        if (t < 16) {
            int rowin = t >> 2, b = t & 3;
            int k = bid*4 + rowin;
            float rowdot = s_part[rowin*2][b] + s_part[rowin*2+1][b];
            float col = 0.f;
            #pragma unroll
            for (int g = 0; g < 16; ++g) col += s_col[t][g];
            float rv = rd[k];
            float r = (rv > 20.f) ? rv : log1pf(expf(rv));
            g_delta[b*D + k] = DT_STEP * (rowdot - col - r*g_t[b*D + k]);
        }
    }
}

// ============ degree-8 polynomial via even/odd Horner ============
__device__ __forceinline__ float poly_eval(float xn, const float* __restrict__ m) {
    float u  = xn*xn;
    float pe = fmaf(fmaf(fmaf(fmaf(m[8],u,m[6]),u,m[4]),u,m[2]),u,m[0]);
    float po = fmaf(fmaf(fmaf(m[7],u,m[5]),u,m[3]),u,m[1]);
    return fmaf(xn, po, pe);
}

// ============ Main fused pass ============
__global__ void __launch_bounds__(256) k_main(const float* __restrict__ x,
                                              float* __restrict__ out) {
    __shared__ float s_red[9];
    int l = blockIdx.x, b = blockIdx.y;
    int tid = threadIdx.x;

    size_t base = ((size_t)b*L + l)*D;
    const float4* xp = (const float4*)(x + base);
    float4*       op = (float4*)(out + base);
    const float4* dp = (const float4*)(g_delta + b*D);

    float4 y0 = xp[tid];
    float4 y1 = xp[tid + 256];
    float4 d0 = dp[tid];
    float4 d1 = dp[tid + 256];
    y0.x += d0.x; y0.y += d0.y; y0.z += d0.z; y0.w += d0.w;
    y1.x += d1.x; y1.y += d1.y; y1.z += d1.z; y1.w += d1.w;

    float sq = y0.x*y0.x + y0.y*y0.y + y0.z*y0.z + y0.w*y0.w
             + y1.x*y1.x + y1.y*y1.y + y1.z*y1.z + y1.w*y1.w;
    #pragma unroll
    for (int off = 16; off; off >>= 1)
        sq += __shfl_xor_sync(0xFFFFFFFFu, sq, off);
    int warp = tid >> 5, lane = tid & 31;
    if (lane == 0) s_red[warp] = sq;
    __syncthreads();
    if (warp == 0) {
        float v = (lane < 8) ? s_red[lane] : 0.f;
        #pragma unroll
        for (int off = 4; off; off >>= 1)
            v += __shfl_xor_sync(0xFFFFFFFFu, v, off);
        if (lane == 0) s_red[8] = v;
    }
    __syncthreads();
    float inv = rsqrtf(fmaxf(s_red[8], 1e-8f));

    float m[DEG+1];
    #pragma unroll
    for (int i = 0; i <= DEG; ++i) m[i] = g_mono[i];

    float4 r0, r1;
    r0.x = y0.x + 0.1f*poly_eval(y0.x*inv, m);
    r0.y = y0.y + 0.1f*poly_eval(y0.y*inv, m);
    r0.z = y0.z + 0.1f*poly_eval(y0.z*inv, m);
    r0.w = y0.w + 0.1f*poly_eval(y0.w*inv, m);
    r1.x = y1.x + 0.1f*poly_eval(y1.x*inv, m);
    r1.y = y1.y + 0.1f*poly_eval(y1.y*inv, m);
    r1.z = y1.z + 0.1f*poly_eval(y1.z*inv, m);
    r1.w = y1.w + 0.1f*poly_eval(y1.w*inv, m);
    __stcs(&op[tid],       r0);   // streaming store: don't evict x from L2
    __stcs(&op[tid + 256], r1);
}

extern "C" void kernel_launch(void* const* d_in, const int* in_sizes, int n_in,
                              void* d_out, int out_size) {
    const float* x   = (const float*)d_in[0];   // [B, L, D]
    const float* ju  = (const float*)d_in[1];   // [D, D]
    const float* rd  = (const float*)d_in[2];   // [D]
    const float* hp  = (const float*)d_in[3];   // [D, D]
    const float* cf  = (const float*)d_in[4];   // [9]
    float* out = (float*)d_out;
    (void)in_sizes; (void)n_in; (void)out_size;

    k_mid<<<NBLK, 256>>>(x, ju, hp, rd, cf);
    k_main<<<dim3(L, B), 256>>>(x, out);
}

// round 10
// speedup vs baseline: 1.4038x; 1.0188x over previous
#include <cuda_runtime.h>
#include <math.h>

#define B 4
#define L 2048
#define D 2048
#define NBLK 512       // persistent-kernel grid (<= 148*4 for residency)
#define ICK 64         // col-term i-chunks (32 rows each)
#define DT_STEP 0.01f
#define DEG 8

// ---- scratch (device globals, no allocation allowed) ----
__device__ float g_xmean[B*D];         // 32 KB
__device__ float g_t[B*D];             // 32 KB
__device__ float g_colpart[ICK*B*D];   // 2 MB
__device__ float g_delta[B*D];         // 32 KB
__device__ float g_mono[DEG+1];        // monomial coeffs of sum c_i T_i

// ---- grid barrier (generation-based: replay-safe, never reset gen) ----
__device__ unsigned g_bar_count = 0;
__device__ unsigned g_bar_gen   = 0;

__device__ __forceinline__ void gridbar() {
    __syncthreads();
    if (threadIdx.x == 0) {
        __threadfence();
        unsigned gen = *(volatile unsigned*)&g_bar_gen;
        unsigned old = atomicAdd(&g_bar_count, 1u);
        if (old == NBLK - 1) {
            g_bar_count = 0;
            __threadfence();
            *(volatile unsigned*)&g_bar_gen = gen + 1;
        } else {
            while (*(volatile unsigned*)&g_bar_gen == gen) {}
        }
        __threadfence();
    }
    __syncthreads();
}

// ============ Fused mid chain ============
__global__ void __launch_bounds__(256, 4) k_mid(const float* __restrict__ x,
                                                const float* __restrict__ ju,
                                                const float* __restrict__ hp,
                                                const float* __restrict__ rd,
                                                const float* __restrict__ cf) {
    __shared__ float s_t[B][32];
    __shared__ float s_part[8][4];
    __shared__ float s_col[16][17];
    __shared__ float4 s_w[8][4];
    const int bid = blockIdx.x;
    const int t   = threadIdx.x;
    const int w = t >> 5, lane = t & 31;

    // ---------- one-time: Chebyshev -> monomial coefficient conversion ----------
    if (bid == NBLK-1 && t == 32) {
        float tp[9], tc[9], tn[9], m[9];
        #pragma unroll
        for (int i = 0; i < 9; ++i) { tp[i]=0.f; tc[i]=0.f; m[i]=0.f; }
        tp[0] = 1.f;              // T0
        tc[1] = 1.f;              // T1
        m[0] = cf[0];
        m[1] = cf[1];
        for (int n = 2; n <= DEG; ++n) {
            for (int i = 0; i < 9; ++i)
                tn[i] = (i ? 2.f*tc[i-1] : 0.f) - tp[i];
            float c = cf[n];
            for (int i = 0; i < 9; ++i) m[i] += c*tn[i];
            for (int i = 0; i < 9; ++i) { tp[i]=tc[i]; tc[i]=tn[i]; }
        }
        for (int i = 0; i < 9; ++i) g_mono[i] = m[i];
    }

    // ---------- P0: full-L column mean, one (b, 16-col) slab per block ----------
    {
        int b    = bid >> 7;           // 0..3
        int dcol = (bid & 127) * 16;   // 16-float slab
        int lsub = t >> 2;             // 0..63
        int c4   = t & 3;              // float4 within slab
        const float4* xp = (const float4*)x;
        size_t base = (((size_t)b*L + lsub)*D + dcol + c4*4) >> 2;
        float4 acc = make_float4(0.f,0.f,0.f,0.f);
        #pragma unroll
        for (int it = 0; it < 32; ++it) {
            float4 v = xp[base + (size_t)it*64*(D/4)];
            acc.x += v.x; acc.y += v.y; acc.z += v.z; acc.w += v.w;
        }
        #pragma unroll
        for (int off = 4; off <= 16; off <<= 1) {
            acc.x += __shfl_xor_sync(0xFFFFFFFFu, acc.x, off);
            acc.y += __shfl_xor_sync(0xFFFFFFFFu, acc.y, off);
            acc.z += __shfl_xor_sync(0xFFFFFFFFu, acc.z, off);
            acc.w += __shfl_xor_sync(0xFFFFFFFFu, acc.w, off);
        }
        if (lane < 4) s_w[w][lane] = acc;
        __syncthreads();
        if (t < 4) {
            float4 s = make_float4(0.f,0.f,0.f,0.f);
            #pragma unroll
            for (int ww = 0; ww < 8; ++ww) {
                float4 v = s_w[ww][t];
                s.x += v.x; s.y += v.y; s.z += v.z; s.w += v.w;
            }
            const float inv = 1.0f/(float)L;
            s.x *= inv; s.y *= inv; s.z *= inv; s.w *= inv;
            *(float4*)&g_xmean[b*D + dcol + t*4] = s;
        }
    }
    gridbar();

    // ---------- P2: t[b,i] = sum_j hp[i,j]*xmean[b,j]  (4 rows/block, 2 warps/row) ----------
    {
        int row  = bid*4 + (w >> 1);
        int half = w & 1;
        const float4* hr = (const float4*)(hp + (size_t)row*D);
        const float4* m0 = (const float4*)(g_xmean + 0*D);
        const float4* m1 = (const float4*)(g_xmean + 1*D);
        const float4* m2 = (const float4*)(g_xmean + 2*D);
        const float4* m3 = (const float4*)(g_xmean + 3*D);
        float a0=0.f,a1=0.f,a2=0.f,a3=0.f;
        #pragma unroll
        for (int it = 0; it < 8; ++it) {
            int j4 = half*256 + it*32 + lane;
            float4 hv = hr[j4];
            float4 v0 = m0[j4], v1 = m1[j4], v2 = m2[j4], v3 = m3[j4];
            a0 += hv.x*v0.x + hv.y*v0.y + hv.z*v0.z + hv.w*v0.w;
            a1 += hv.x*v1.x + hv.y*v1.y + hv.z*v1.z + hv.w*v1.w;
            a2 += hv.x*v2.x + hv.y*v2.y + hv.z*v2.z + hv.w*v2.w;
            a3 += hv.x*v3.x + hv.y*v3.y + hv.z*v3.z + hv.w*v3.w;
        }
        #pragma unroll
        for (int off = 16; off; off >>= 1) {
            a0 += __shfl_xor_sync(0xFFFFFFFFu, a0, off);
            a1 += __shfl_xor_sync(0xFFFFFFFFu, a1, off);
            a2 += __shfl_xor_sync(0xFFFFFFFFu, a2, off);
            a3 += __shfl_xor_sync(0xFFFFFFFFu, a3, off);
        }
        if (lane == 0) { s_part[w][0]=a0; s_part[w][1]=a1; s_part[w][2]=a2; s_part[w][3]=a3; }
        __syncthreads();
        if (t < 16) {
            int rowin = t >> 2, b = t & 3;
            float s = s_part[rowin*2][b] + s_part[rowin*2+1][b];
            g_t[b*D + bid*4 + rowin] = s;
        }
    }
    gridbar();

    // ---------- P3: col partials: sum_{i in chunk} t[b,i]*ju[i,k] ----------
    {
        int ktile = bid >> 6;
        int ick   = bid & 63;
        int i0    = ick*32;
        if (t < B*32) {
            int b = t >> 5, ii = t & 31;
            s_t[b][ii] = g_t[b*D + i0 + ii];
        }
        __syncthreads();
        int k = ktile*256 + t;
        float a0=0.f,a1=0.f,a2=0.f,a3=0.f;
        #pragma unroll
        for (int ii = 0; ii < 32; ++ii) {
            float v = ju[(size_t)(i0+ii)*D + k];   // default: keep ju L2-resident for P4
            a0 += s_t[0][ii]*v;
            a1 += s_t[1][ii]*v;
            a2 += s_t[2][ii]*v;
            a3 += s_t[3][ii]*v;
        }
        g_colpart[(size_t)(ick*B + 0)*D + k] = a0;
        g_colpart[(size_t)(ick*B + 1)*D + k] = a1;
        g_colpart[(size_t)(ick*B + 2)*D + k] = a2;
        g_colpart[(size_t)(ick*B + 3)*D + k] = a3;
    }
    gridbar();

    // ---------- P4: row dots + parallel col-sum + finalize delta ----------
    {
        int row  = bid*4 + (w >> 1);
        int half = w & 1;
        const float4* jr = (const float4*)(ju + (size_t)row*D);
        const float4* t0 = (const float4*)(g_t + 0*D);
        const float4* t1 = (const float4*)(g_t + 1*D);
        const float4* t2 = (const float4*)(g_t + 2*D);
        const float4* t3 = (const float4*)(g_t + 3*D);
        float a0=0.f,a1=0.f,a2=0.f,a3=0.f;
        #pragma unroll
        for (int it = 0; it < 8; ++it) {
            int j4 = half*256 + it*32 + lane;
            float4 jv = jr[j4];
            float4 v0 = t0[j4], v1 = t1[j4], v2 = t2[j4], v3 = t3[j4];
            a0 += jv.x*v0.x + jv.y*v0.y + jv.z*v0.z + jv.w*v0.w;
            a1 += jv.x*v1.x + jv.y*v1.y + jv.z*v1.z + jv.w*v1.w;
            a2 += jv.x*v2.x + jv.y*v2.y + jv.z*v2.z + jv.w*v2.w;
            a3 += jv.x*v3.x + jv.y*v3.y + jv.z*v3.z + jv.w*v3.w;
        }
        #pragma unroll
        for (int off = 16; off; off >>= 1) {
            a0 += __shfl_xor_sync(0xFFFFFFFFu, a0, off);
            a1 += __shfl_xor_sync(0xFFFFFFFFu, a1, off);
            a2 += __shfl_xor_sync(0xFFFFFFFFu, a2, off);
            a3 += __shfl_xor_sync(0xFFFFFFFFu, a3, off);
        }
        if (lane == 0) { s_part[w][0]=a0; s_part[w][1]=a1; s_part[w][2]=a2; s_part[w][3]=a3; }

        // parallel colpart reduction
        {
            int p = t >> 4;          // 0..15 pair (rowin<<2)|b
            int g = t & 15;          // chunk group of 4
            int b = p & 3, rowin = p >> 2;
            int k = bid*4 + rowin;
            float s = 0.f;
            #pragma unroll
            for (int c = 0; c < 4; ++c)
                s += g_colpart[(size_t)((g*4+c)*B + b)*D + k];
            s_col[p][g] = s;
        }
        __syncthreads();
        if (t < 16) {
            int rowin = t >> 2, b = t & 3;
            int k = bid*4 + rowin;
            float rowdot = s_part[rowin*2][b] + s_part[rowin*2+1][b];
            float col = 0.f;
            #pragma unroll
            for (int g = 0; g < 16; ++g) col += s_col[t][g];
            float rv = rd[k];
            float r = (rv > 20.f) ? rv : log1pf(expf(rv));
            g_delta[b*D + k] = DT_STEP * (rowdot - col - r*g_t[b*D + k]);
        }
    }
}

// ============ degree-8 polynomial via even/odd Horner ============
__device__ __forceinline__ float poly_eval(float xn, const float* __restrict__ m) {
    float u  = xn*xn;
    float pe = fmaf(fmaf(fmaf(fmaf(m[8],u,m[6]),u,m[4]),u,m[2]),u,m[0]);
    float po = fmaf(fmaf(fmaf(m[7],u,m[5]),u,m[3]),u,m[1]);
    return fmaf(xn, po, pe);
}

// ============ Main fused pass: 4 L-rows per block, delta in registers ============
__global__ void __launch_bounds__(256) k_main(const float* __restrict__ x,
                                              float* __restrict__ out) {
    __shared__ float s_red[9];
    int b = blockIdx.y;
    int tid = threadIdx.x;
    int warp = tid >> 5, lane = tid & 31;

    // per-thread delta slice (2 float4) and poly coeffs — loaded once per block
    const float4* dp = (const float4*)(g_delta + b*D);
    float4 d0 = dp[tid];
    float4 d1 = dp[tid + 256];
    float m[DEG+1];
    #pragma unroll
    for (int i = 0; i <= DEG; ++i) m[i] = g_mono[i];

    size_t row0 = ((size_t)b*L + blockIdx.x*4)*D;

    #pragma unroll
    for (int r = 0; r < 4; ++r) {
        const float4* xp = (const float4*)(x + row0 + (size_t)r*D);
        float4*       op = (float4*)(out + row0 + (size_t)r*D);

        float4 y0 = xp[tid];
        float4 y1 = xp[tid + 256];
        y0.x += d0.x; y0.y += d0.y; y0.z += d0.z; y0.w += d0.w;
        y1.x += d1.x; y1.y += d1.y; y1.z += d1.z; y1.w += d1.w;

        float sq = y0.x*y0.x + y0.y*y0.y + y0.z*y0.z + y0.w*y0.w
                 + y1.x*y1.x + y1.y*y1.y + y1.z*y1.z + y1.w*y1.w;
        #pragma unroll
        for (int off = 16; off; off >>= 1)
            sq += __shfl_xor_sync(0xFFFFFFFFu, sq, off);
        if (r) __syncthreads();         // protect s_red reuse across iterations
        if (lane == 0) s_red[warp] = sq;
        __syncthreads();
        if (warp == 0) {
            float v = (lane < 8) ? s_red[lane] : 0.f;
            #pragma unroll
            for (int off = 4; off; off >>= 1)
                v += __shfl_xor_sync(0xFFFFFFFFu, v, off);
            if (lane == 0) s_red[8] = v;
        }
        __syncthreads();
        float inv = rsqrtf(fmaxf(s_red[8], 1e-8f));

        float4 r0, r1;
        r0.x = y0.x + 0.1f*poly_eval(y0.x*inv, m);
        r0.y = y0.y + 0.1f*poly_eval(y0.y*inv, m);
        r0.z = y0.z + 0.1f*poly_eval(y0.z*inv, m);
        r0.w = y0.w + 0.1f*poly_eval(y0.w*inv, m);
        r1.x = y1.x + 0.1f*poly_eval(y1.x*inv, m);
        r1.y = y1.y + 0.1f*poly_eval(y1.y*inv, m);
        r1.z = y1.z + 0.1f*poly_eval(y1.z*inv, m);
        r1.w = y1.w + 0.1f*poly_eval(y1.w*inv, m);
        __stcs(&op[tid],       r0);   // streaming: keep x resident instead of out
        __stcs(&op[tid + 256], r1);
    }
}

extern "C" void kernel_launch(void* const* d_in, const int* in_sizes, int n_in,
                              void* d_out, int out_size) {
    const float* x   = (const float*)d_in[0];   // [B, L, D]
    const float* ju  = (const float*)d_in[1];   // [D, D]
    const float* rd  = (const float*)d_in[2];   // [D]
    const float* hp  = (const float*)d_in[3];   // [D, D]
    const float* cf  = (const float*)d_in[4];   // [9]
    float* out = (float*)d_out;
    (void)in_sizes; (void)n_in; (void)out_size;

    k_mid<<<NBLK, 256>>>(x, ju, hp, rd, cf);
    k_main<<<dim3(L/4, B), 256>>>(x, out);
}